// round 9
// baseline (speedup 1.0000x reference)
#include <cuda_runtime.h>
#include <cstdint>

#define BATCH 8
#define SEQ   1024
#define DIM   1024
#define HEADS 16
#define DH    64
#define INNER 1024
#define QKV_STRIDE (3 * INNER)

// Scratch (static device arrays: the sanctioned no-alloc workaround)
__device__ float g_qkv[(size_t)BATCH * SEQ * 3 * INNER];
__device__ float g_att[(size_t)BATCH * SEQ * INNER];

// ---------------------------------------------------------------------------
// tf32 helpers
// ---------------------------------------------------------------------------
__device__ __forceinline__ uint32_t f2t(float x) {
    uint32_t r;
    asm("cvt.rna.tf32.f32 %0, %1;" : "=r"(r) : "f"(x));
    return r;
}
__device__ __forceinline__ uint4 f2t4(float4 v) {
    return make_uint4(f2t(v.x), f2t(v.y), f2t(v.z), f2t(v.w));
}

// m16n8k8 tf32 MMA, fp32 accumulate. A row-major, B col-major.
__device__ __forceinline__ void mma8(float* c, const uint32_t* a, const uint32_t* b) {
    asm volatile(
        "mma.sync.aligned.m16n8k8.row.col.f32.tf32.tf32.f32 "
        "{%0,%1,%2,%3}, {%4,%5,%6,%7}, {%8,%9}, {%0,%1,%2,%3};\n"
        : "+f"(c[0]), "+f"(c[1]), "+f"(c[2]), "+f"(c[3])
        : "r"(a[0]), "r"(a[1]), "r"(a[2]), "r"(a[3]), "r"(b[0]), "r"(b[1]));
}

// ---------------------------------------------------------------------------
// tf32 GEMM: C = A*B (+bias). BM=BN=128, BK=32, 256 threads, 8 warps (2m x 4n),
// warp tile 64x32. A staged in XOR-swizzled fragment layout (uint4 stores,
// conflict-free frag loads). B row-major padded (LDB=136, conflict-free).
// Register-staged global prefetch, double-buffered smem, 1 sync per chunk.
// ---------------------------------------------------------------------------
#define LDB 136
#define ASZ 4096                 // 8mt * 4kb * 4reg * 32lane words
#define BSZ (32 * LDB)           // 4352 words
#define GEMM_SMEM ((2 * ASZ + 2 * BSZ) * 4)   // 67584 bytes

__global__ __launch_bounds__(256) void gemm_tf32(
    const float* __restrict__ A, const float* __restrict__ B,
    const float* __restrict__ bias, float* __restrict__ C,
    int M, int N, int K)
{
    extern __shared__ uint32_t sm[];
    uint32_t* Asb[2] = {sm, sm + ASZ};
    uint32_t* Bsb[2] = {sm + 2 * ASZ, sm + 2 * ASZ + BSZ};

    const int tid  = threadIdx.x;
    const int lane = tid & 31;
    const int warp = tid >> 5;
    const int row0 = blockIdx.y * 128;
    const int col0 = blockIdx.x * 128;

    const int wmt = (warp >> 2) * 4;   // mtile base (4 mtiles = 64 rows)
    const int wn  = (warp & 3) * 32;   // warp col base
    const int r4 = lane >> 2, c4 = lane & 3;

    float acc[4][4][4] = {};
    float4 ra[4], rb[4];

    // ---- global load into regs ----
    #define LOADG(kt) do {                                                     \
        _Pragma("unroll")                                                      \
        for (int it = 0; it < 4; it++) {                                       \
            int idx = it * 256 + tid;                                          \
            int m = idx >> 3, q = idx & 7;                                     \
            ra[it] = *(const float4*)(A + (size_t)(row0 + m) * K + (kt) + q * 4); \
            int nq = idx & 31, kr = idx >> 5;                                  \
            rb[it] = *(const float4*)(B + (size_t)((kt) + kr) * N + col0 + nq * 4); \
        } } while (0)

    // ---- store staged regs to smem buffer s (tf32 convert) ----
    #define STORES(s) do {                                                     \
        _Pragma("unroll")                                                      \
        for (int it = 0; it < 4; it++) {                                       \
            int idx = it * 256 + tid;                                          \
            int m = idx >> 3, q = idx & 7;                                     \
            int kb = q >> 1, khalf = q & 1;                                    \
            int regb = ((m >> 3) & 1) + 2 * khalf;                             \
            int word = (((m >> 4) * 4 + kb) * 4 + regb) * 32 +                 \
                       (((m & 7) * 4) ^ (q * 4));                              \
            *(uint4*)&Asb[s][word] = f2t4(ra[it]);                             \
            int nq = idx & 31, kr = idx >> 5;                                  \
            *(uint4*)&Bsb[s][kr * LDB + nq * 4] = f2t4(rb[it]);                \
        } } while (0)

    LOADG(0);
    STORES(0);
    const int nch = K / 32;

    for (int c = 0; c < nch; c++) {
        const int s = c & 1;
        __syncthreads();
        if (c + 1 < nch) LOADG((c + 1) * 32);

        const uint32_t* As = Asb[s];
        const uint32_t* Bs = Bsb[s];
        #pragma unroll
        for (int kb = 0; kb < 4; kb++) {
            uint32_t af[4][4], bf[4][2];
            const int sw0 = lane ^ (kb * 8);
            const int sw1 = lane ^ (kb * 8 + 4);
            #pragma unroll
            for (int fm = 0; fm < 4; fm++) {
                const int base = (((wmt + fm) * 4 + kb) * 4) * 32;
                af[fm][0] = As[base + sw0];
                af[fm][1] = As[base + 32 + sw0];
                af[fm][2] = As[base + 64 + sw1];
                af[fm][3] = As[base + 96 + sw1];
            }
            #pragma unroll
            for (int fn = 0; fn < 4; fn++) {
                const int n = wn + fn * 8 + r4;
                bf[fn][0] = Bs[(kb * 8 + c4) * LDB + n];
                bf[fn][1] = Bs[(kb * 8 + c4 + 4) * LDB + n];
            }
            #pragma unroll
            for (int fm = 0; fm < 4; fm++)
                #pragma unroll
                for (int fn = 0; fn < 4; fn++)
                    mma8(acc[fm][fn], af[fm], bf[fn]);
        }
        if (c + 1 < nch) STORES(s ^ 1);
    }

    // Epilogue
    #pragma unroll
    for (int fm = 0; fm < 4; fm++) {
        #pragma unroll
        for (int fn = 0; fn < 4; fn++) {
            int row = row0 + (wmt + fm) * 16 + r4;
            int col = col0 + wn + fn * 8 + c4 * 2;
            float b0 = 0.f, b1 = 0.f;
            if (bias) { b0 = bias[col]; b1 = bias[col + 1]; }
            *(float2*)&C[(size_t)row * N + col] =
                make_float2(acc[fm][fn][0] + b0, acc[fm][fn][1] + b1);
            *(float2*)&C[(size_t)(row + 8) * N + col] =
                make_float2(acc[fm][fn][2] + b0, acc[fm][fn][3] + b1);
        }
    }
    #undef LOADG
    #undef STORES
}

// ---------------------------------------------------------------------------
// Flash attention, tf32 MMA. CTA = 128 query rows of one (b,h); 8 warps,
// warp owns 16 rows x all 64 cols. Q frags in registers (loaded once).
// S stays in registers; softmax via quad shuffles; P round-trips through a
// per-warp smem fragment region (__syncwarp only). 2 syncthreads per KV tile.
// ---------------------------------------------------------------------------
#define KVPAD 68
#define ATTN_SMEM ((2 * 64 * KVPAD + 8 * 1024) * 4)   // 67584 bytes

__global__ __launch_bounds__(256) void attn_tf32(
    const float* __restrict__ qkv, float* __restrict__ out)
{
    extern __shared__ uint32_t sm[];
    uint32_t* Ksm = sm;                     // [j(64)][KVPAD] tf32  (b-frag: K[j][d])
    uint32_t* Vsm = sm + 64 * KVPAD;        // [d(64)][KVPAD] tf32  (V transposed)
    uint32_t* Psm = sm + 2 * 64 * KVPAD;    // per-warp [kb(8)][reg(4)][lane(32)]

    const int tid  = threadIdx.x;
    const int lane = tid & 31;
    const int warp = tid >> 5;
    const int r4 = lane >> 2, c4 = lane & 3;
    const int qt = blockIdx.x, h = blockIdx.y, b = blockIdx.z;
    const int qr0 = qt * 128 + warp * 16;

    const float* qbase = qkv + ((size_t)b * SEQ + qr0) * QKV_STRIDE + h * DH;
    const float* kbase = qkv + (size_t)b * SEQ * QKV_STRIDE + INNER     + h * DH;
    const float* vbase = qkv + (size_t)b * SEQ * QKV_STRIDE + 2 * INNER + h * DH;

    // Q fragments in registers, pre-scaled by 1/sqrt(Dh)=0.125
    uint32_t qf[8][4];
    #pragma unroll
    for (int kb = 0; kb < 8; kb++) {
        const int col = kb * 8 + c4;
        qf[kb][0] = f2t(0.125f * qbase[(size_t)r4 * QKV_STRIDE + col]);
        qf[kb][1] = f2t(0.125f * qbase[(size_t)(r4 + 8) * QKV_STRIDE + col]);
        qf[kb][2] = f2t(0.125f * qbase[(size_t)r4 * QKV_STRIDE + col + 4]);
        qf[kb][3] = f2t(0.125f * qbase[(size_t)(r4 + 8) * QKV_STRIDE + col + 4]);
    }

    float m0 = -3.0e38f, m1 = -3.0e38f, l0 = 0.f, l1 = 0.f;
    float o[8][4] = {};
    uint32_t* Pw = Psm + warp * 1024;

    for (int t = 0; t < 16; t++) {
        __syncthreads();   // previous tile fully consumed
        const float* kt_ = kbase + (size_t)t * 64 * QKV_STRIDE;
        const float* vt_ = vbase + (size_t)t * 64 * QKV_STRIDE;
        #pragma unroll
        for (int it = 0; it < 4; it++) {
            int idx = it * 256 + tid;
            int j = idx >> 4, dq = idx & 15;
            float4 kv = *(const float4*)(kt_ + (size_t)j * QKV_STRIDE + dq * 4);
            *(uint4*)&Ksm[j * KVPAD + dq * 4] = f2t4(kv);
            float4 vv = *(const float4*)(vt_ + (size_t)j * QKV_STRIDE + dq * 4);
            Vsm[(dq * 4 + 0) * KVPAD + j] = f2t(vv.x);
            Vsm[(dq * 4 + 1) * KVPAD + j] = f2t(vv.y);
            Vsm[(dq * 4 + 2) * KVPAD + j] = f2t(vv.z);
            Vsm[(dq * 4 + 3) * KVPAD + j] = f2t(vv.w);
        }
        __syncthreads();

        // ---- S = Q * K^T : warp's 16 rows x 64 cols, in registers ----
        float s[8][4] = {};
        #pragma unroll
        for (int kb = 0; kb < 8; kb++) {
            #pragma unroll
            for (int fn = 0; fn < 8; fn++) {
                uint32_t bb[2];
                bb[0] = Ksm[(fn * 8 + r4) * KVPAD + kb * 8 + c4];
                bb[1] = Ksm[(fn * 8 + r4) * KVPAD + kb * 8 + c4 + 4];
                mma8(s[fn], qf[kb], bb);
            }
        }

        // ---- online softmax, fully in registers (quad = one row) ----
        float mt0 = -3.0e38f, mt1 = -3.0e38f;
        #pragma unroll
        for (int fn = 0; fn < 8; fn++) {
            mt0 = fmaxf(mt0, fmaxf(s[fn][0], s[fn][1]));
            mt1 = fmaxf(mt1, fmaxf(s[fn][2], s[fn][3]));
        }
        mt0 = fmaxf(mt0, __shfl_xor_sync(0xffffffffu, mt0, 1));
        mt0 = fmaxf(mt0, __shfl_xor_sync(0xffffffffu, mt0, 2));
        mt1 = fmaxf(mt1, __shfl_xor_sync(0xffffffffu, mt1, 1));
        mt1 = fmaxf(mt1, __shfl_xor_sync(0xffffffffu, mt1, 2));
        const float mn0 = fmaxf(m0, mt0), mn1 = fmaxf(m1, mt1);
        const float al0 = __expf(m0 - mn0), al1 = __expf(m1 - mn1);
        float ls0 = 0.f, ls1 = 0.f;
        #pragma unroll
        for (int fn = 0; fn < 8; fn++) {
            s[fn][0] = __expf(s[fn][0] - mn0); ls0 += s[fn][0];
            s[fn][1] = __expf(s[fn][1] - mn0); ls0 += s[fn][1];
            s[fn][2] = __expf(s[fn][2] - mn1); ls1 += s[fn][2];
            s[fn][3] = __expf(s[fn][3] - mn1); ls1 += s[fn][3];
        }
        ls0 += __shfl_xor_sync(0xffffffffu, ls0, 1);
        ls0 += __shfl_xor_sync(0xffffffffu, ls0, 2);
        ls1 += __shfl_xor_sync(0xffffffffu, ls1, 1);
        ls1 += __shfl_xor_sync(0xffffffffu, ls1, 2);
        l0 = l0 * al0 + ls0;  l1 = l1 * al1 + ls1;
        m0 = mn0;  m1 = mn1;

        // rescale running O
        #pragma unroll
        for (int fn = 0; fn < 8; fn++) {
            o[fn][0] *= al0; o[fn][1] *= al0;
            o[fn][2] *= al1; o[fn][3] *= al1;
        }

        // ---- P c-frag -> a-frag via per-warp smem ----
        {
            const int lp0 = r4 * 4 + 2 * (c4 & 1);
            const int rb  = 2 * (c4 >> 1);
            #pragma unroll
            for (int fn = 0; fn < 8; fn++) {
                Pw[(fn * 4 + rb) * 32 + lp0]         = f2t(s[fn][0]);
                Pw[(fn * 4 + rb) * 32 + lp0 + 1]     = f2t(s[fn][1]);
                Pw[(fn * 4 + rb + 1) * 32 + lp0]     = f2t(s[fn][2]);
                Pw[(fn * 4 + rb + 1) * 32 + lp0 + 1] = f2t(s[fn][3]);
            }
        }
        __syncwarp();

        // ---- O += P * V ----
        #pragma unroll
        for (int kb = 0; kb < 8; kb++) {
            uint32_t a[4];
            a[0] = Pw[(kb * 4 + 0) * 32 + lane];
            a[1] = Pw[(kb * 4 + 1) * 32 + lane];
            a[2] = Pw[(kb * 4 + 2) * 32 + lane];
            a[3] = Pw[(kb * 4 + 3) * 32 + lane];
            #pragma unroll
            for (int fn = 0; fn < 8; fn++) {
                uint32_t bb[2];
                bb[0] = Vsm[(fn * 8 + r4) * KVPAD + kb * 8 + c4];
                bb[1] = Vsm[(fn * 8 + r4) * KVPAD + kb * 8 + c4 + 4];
                mma8(o[fn], a, bb);
            }
        }
        __syncwarp();   // P reads done before next tile's P writes
    }

    // ---- normalize and write merged-heads [B, N, INNER] ----
    const float inv0 = 1.f / l0, inv1 = 1.f / l1;
    float* ob = out + ((size_t)b * SEQ + qr0) * INNER + h * DH;
    #pragma unroll
    for (int fn = 0; fn < 8; fn++) {
        const int col = fn * 8 + 2 * c4;
        *(float2*)&ob[(size_t)r4 * INNER + col] =
            make_float2(o[fn][0] * inv0, o[fn][1] * inv0);
        *(float2*)&ob[(size_t)(r4 + 8) * INNER + col] =
            make_float2(o[fn][2] * inv1, o[fn][3] * inv1);
    }
}

// ---------------------------------------------------------------------------
// Launch
// ---------------------------------------------------------------------------
extern "C" void kernel_launch(void* const* d_in, const int* in_sizes, int n_in,
                              void* d_out, int out_size)
{
    const float* x      = (const float*)d_in[0];
    const float* w_qkv  = (const float*)d_in[1];
    const float* w_out  = (const float*)d_in[2];
    const float* b_out  = (const float*)d_in[3];
    float* out = (float*)d_out;

    float* qkv; cudaGetSymbolAddress((void**)&qkv, g_qkv);
    float* att; cudaGetSymbolAddress((void**)&att, g_att);

    const int M = BATCH * SEQ;   // 8192

    cudaFuncSetAttribute(gemm_tf32, cudaFuncAttributeMaxDynamicSharedMemorySize, GEMM_SMEM);
    cudaFuncSetAttribute(attn_tf32, cudaFuncAttributeMaxDynamicSharedMemorySize, ATTN_SMEM);

    // 1) QKV projection: [8192,1024] x [1024,3072]
    gemm_tf32<<<dim3(3 * INNER / 128, M / 128), 256, GEMM_SMEM>>>(
        x, w_qkv, nullptr, qkv, M, 3 * INNER, DIM);

    // 2) Flash attention
    attn_tf32<<<dim3(SEQ / 128, HEADS, BATCH), 256, ATTN_SMEM>>>(qkv, att);

    // 3) Output projection: [8192,1024] x [1024,1024] + bias
    gemm_tf32<<<dim3(DIM / 128, M / 128), 256, GEMM_SMEM>>>(
        att, w_out, b_out, out, M, DIM, INNER);
}

// round 10
// speedup vs baseline: 1.4248x; 1.4248x over previous
#include <cuda_runtime.h>
#include <cstdint>

#define BATCH 8
#define SEQ   1024
#define DIM   1024
#define HEADS 16
#define DH    64
#define INNER 1024
#define QKV_STRIDE (3 * INNER)

// Scratch (static device arrays: the sanctioned no-alloc workaround)
__device__ uint32_t g_qkv[(size_t)BATCH * SEQ * 3 * INNER];   // tf32 bits
__device__ uint32_t g_att[(size_t)BATCH * SEQ * INNER];       // tf32 bits
__device__ uint32_t g_xt[(size_t)BATCH * SEQ * DIM];          // x as tf32 bits
__device__ uint32_t g_wqkvt[(size_t)DIM * 3 * INNER];         // w_qkv as tf32 bits
__device__ uint32_t g_woutt[(size_t)INNER * DIM];             // w_out as tf32 bits

// ---------------------------------------------------------------------------
// tf32 helpers
// ---------------------------------------------------------------------------
__device__ __forceinline__ uint32_t f2t(float x) {
    uint32_t r;
    asm("cvt.rna.tf32.f32 %0, %1;" : "=r"(r) : "f"(x));
    return r;
}
__device__ __forceinline__ uint4 f2t4(float4 v) {
    return make_uint4(f2t(v.x), f2t(v.y), f2t(v.z), f2t(v.w));
}
__device__ __forceinline__ uint32_t smem_u32(const void* p) {
    uint32_t a;
    asm("{ .reg .u64 t; cvta.to.shared.u64 t, %1; cvt.u32.u64 %0, t; }" : "=r"(a) : "l"(p));
    return a;
}
__device__ __forceinline__ void cpasync16(uint32_t s, const void* g) {
    asm volatile("cp.async.cg.shared.global [%0], [%1], 16;" :: "r"(s), "l"(g));
}

// m16n8k8 tf32 MMA, fp32 accumulate. A row-major, B col-major.
__device__ __forceinline__ void mma8(float* c, const uint32_t* a, const uint32_t* b) {
    asm volatile(
        "mma.sync.aligned.m16n8k8.row.col.f32.tf32.tf32.f32 "
        "{%0,%1,%2,%3}, {%4,%5,%6,%7}, {%8,%9}, {%0,%1,%2,%3};\n"
        : "+f"(c[0]), "+f"(c[1]), "+f"(c[2]), "+f"(c[3])
        : "r"(a[0]), "r"(a[1]), "r"(a[2]), "r"(a[3]), "r"(b[0]), "r"(b[1]));
}

// ---------------------------------------------------------------------------
// Elementwise fp32 -> tf32-bits converter (grid-stride, float4)
// ---------------------------------------------------------------------------
__global__ void conv_tf32(const float4* __restrict__ in, uint4* __restrict__ out, int n4) {
    for (int i = blockIdx.x * blockDim.x + threadIdx.x; i < n4; i += gridDim.x * blockDim.x)
        out[i] = f2t4(in[i]);
}

// ---------------------------------------------------------------------------
// tf32 GEMM on pre-converted bits: C = A*B (+bias).
// BM=BN=128, BK=16, 256 threads, 8 warps (2m x 4n), warp tile 64x32.
// 3-stage cp.async pipeline; As [m][k] LDA=20, Bs [k][n] LDB=136 (both
// conflict-free for fragment loads). out_tf32: epilogue emits tf32 bits.
// ---------------------------------------------------------------------------
#define LDA 20
#define LDB 136
#define STG_WORDS (128 * LDA + 16 * LDB)          // 4736 words / stage
#define GEMM_SMEM (3 * STG_WORDS * 4)             // 56832 bytes

__global__ __launch_bounds__(256, 2) void gemm_tf32(
    const uint32_t* __restrict__ A, const uint32_t* __restrict__ B,
    const float* __restrict__ bias, uint32_t* __restrict__ C,
    int M, int N, int K, int out_tf32)
{
    extern __shared__ uint32_t sm[];
    const uint32_t sbase = smem_u32(sm);

    const int tid  = threadIdx.x;
    const int lane = tid & 31;
    const int warp = tid >> 5;
    const int row0 = blockIdx.y * 128;
    const int col0 = blockIdx.x * 128;

    const int wm = (warp >> 2) * 64;
    const int wn = (warp & 3) * 32;
    const int r4 = lane >> 2, c4 = lane & 3;

    float acc[4][4][4] = {};

    const int nch = K / 16;

    // issue cp.async loads for chunk c into stage st
    auto issue = [&](int c, int st) {
        const int kt = c * 16;
        const uint32_t abase = sbase + st * STG_WORDS * 4;
        const uint32_t bbase = abase + 128 * LDA * 4;
        #pragma unroll
        for (int it = 0; it < 2; it++) {
            int idx = tid + it * 256;                 // 0..511
            int m = idx >> 2, k0 = (idx & 3) * 4;
            cpasync16(abase + (m * LDA + k0) * 4,
                      A + (size_t)(row0 + m) * K + kt + k0);
            int kr = idx >> 5, nq = (idx & 31) * 4;
            cpasync16(bbase + (kr * LDB + nq) * 4,
                      B + (size_t)(kt + kr) * N + col0 + nq);
        }
        asm volatile("cp.async.commit_group;" ::: "memory");
    };

    issue(0, 0);
    issue(1, 1);

    for (int c = 0; c < nch; c++) {
        if (c < nch - 1)
            asm volatile("cp.async.wait_group 1;" ::: "memory");
        else
            asm volatile("cp.async.wait_group 0;" ::: "memory");
        __syncthreads();

        const uint32_t* As = sm + (c % 3) * STG_WORDS;
        const uint32_t* Bs = As + 128 * LDA;

        #pragma unroll
        for (int kk = 0; kk < 2; kk++) {
            const int kc = kk * 8 + c4;
            uint32_t a[4][4], b[4][2];
            #pragma unroll
            for (int fm = 0; fm < 4; fm++) {
                const int r = wm + fm * 16 + r4;
                a[fm][0] = As[r * LDA + kc];
                a[fm][1] = As[(r + 8) * LDA + kc];
                a[fm][2] = As[r * LDA + kc + 4];
                a[fm][3] = As[(r + 8) * LDA + kc + 4];
            }
            #pragma unroll
            for (int fn = 0; fn < 4; fn++) {
                const int n = wn + fn * 8 + r4;
                b[fn][0] = Bs[kc * LDB + n];
                b[fn][1] = Bs[(kc + 4) * LDB + n];
            }
            #pragma unroll
            for (int fm = 0; fm < 4; fm++)
                #pragma unroll
                for (int fn = 0; fn < 4; fn++)
                    mma8(acc[fm][fn], a[fm], b[fn]);
        }

        if (c + 2 < nch) issue(c + 2, (c + 2) % 3);
    }

    // Epilogue
    #pragma unroll
    for (int fm = 0; fm < 4; fm++) {
        #pragma unroll
        for (int fn = 0; fn < 4; fn++) {
            const int row = row0 + wm + fm * 16 + r4;
            const int col = col0 + wn + fn * 8 + c4 * 2;
            uint32_t* c0 = C + (size_t)row * N + col;
            uint32_t* c1 = C + (size_t)(row + 8) * N + col;
            if (out_tf32) {
                *(uint2*)c0 = make_uint2(f2t(acc[fm][fn][0]), f2t(acc[fm][fn][1]));
                *(uint2*)c1 = make_uint2(f2t(acc[fm][fn][2]), f2t(acc[fm][fn][3]));
            } else {
                float b0 = 0.f, b1 = 0.f;
                if (bias) { b0 = bias[col]; b1 = bias[col + 1]; }
                *(float2*)c0 = make_float2(acc[fm][fn][0] + b0, acc[fm][fn][1] + b1);
                *(float2*)c1 = make_float2(acc[fm][fn][2] + b0, acc[fm][fn][3] + b1);
            }
        }
    }
}

// ---------------------------------------------------------------------------
// Flash attention on tf32-bit qkv. CTA = 128 query rows of one (b,h); 8 warps,
// warp owns 16 rows x 64 cols. Q frags in registers; S in registers; softmax
// via quad shuffles; P through per-warp smem (__syncwarp). Output: tf32 bits.
// ---------------------------------------------------------------------------
#define KVPAD 68
#define ATTN_SMEM ((2 * 64 * KVPAD + 8 * 1024) * 4)   // 67584 bytes

__global__ __launch_bounds__(256) void attn_tf32(
    const uint32_t* __restrict__ qkv, uint32_t* __restrict__ out)
{
    extern __shared__ uint32_t sm[];
    uint32_t* Ksm = sm;                     // [j(64)][KVPAD]
    uint32_t* Vsm = sm + 64 * KVPAD;        // [d(64)][KVPAD] (V transposed)
    uint32_t* Psm = sm + 2 * 64 * KVPAD;    // per-warp [kb(8)][reg(4)][lane(32)]

    const int tid  = threadIdx.x;
    const int lane = tid & 31;
    const int warp = tid >> 5;
    const int r4 = lane >> 2, c4 = lane & 3;
    const int qt = blockIdx.x, h = blockIdx.y, b = blockIdx.z;
    const int qr0 = qt * 128 + warp * 16;

    const uint32_t* qbase = qkv + ((size_t)b * SEQ + qr0) * QKV_STRIDE + h * DH;
    const uint32_t* kbase = qkv + (size_t)b * SEQ * QKV_STRIDE + INNER     + h * DH;
    const uint32_t* vbase = qkv + (size_t)b * SEQ * QKV_STRIDE + 2 * INNER + h * DH;

    // Q fragments (bits already tf32; *0.125 is exact -> still tf32-valid)
    uint32_t qf[8][4];
    #pragma unroll
    for (int kb = 0; kb < 8; kb++) {
        const int col = kb * 8 + c4;
        qf[kb][0] = __float_as_uint(__uint_as_float(qbase[(size_t)r4 * QKV_STRIDE + col]) * 0.125f);
        qf[kb][1] = __float_as_uint(__uint_as_float(qbase[(size_t)(r4 + 8) * QKV_STRIDE + col]) * 0.125f);
        qf[kb][2] = __float_as_uint(__uint_as_float(qbase[(size_t)r4 * QKV_STRIDE + col + 4]) * 0.125f);
        qf[kb][3] = __float_as_uint(__uint_as_float(qbase[(size_t)(r4 + 8) * QKV_STRIDE + col + 4]) * 0.125f);
    }

    float m0 = -3.0e38f, m1 = -3.0e38f, l0 = 0.f, l1 = 0.f;
    float o[8][4] = {};
    uint32_t* Pw = Psm + warp * 1024;

    for (int t = 0; t < 16; t++) {
        __syncthreads();
        const uint32_t* kt_ = kbase + (size_t)t * 64 * QKV_STRIDE;
        const uint32_t* vt_ = vbase + (size_t)t * 64 * QKV_STRIDE;
        #pragma unroll
        for (int it = 0; it < 4; it++) {
            int idx = it * 256 + tid;
            int j = idx >> 4, dq = idx & 15;
            uint4 kv = *(const uint4*)(kt_ + (size_t)j * QKV_STRIDE + dq * 4);
            *(uint4*)&Ksm[j * KVPAD + dq * 4] = kv;
            uint4 vv = *(const uint4*)(vt_ + (size_t)j * QKV_STRIDE + dq * 4);
            Vsm[(dq * 4 + 0) * KVPAD + j] = vv.x;
            Vsm[(dq * 4 + 1) * KVPAD + j] = vv.y;
            Vsm[(dq * 4 + 2) * KVPAD + j] = vv.z;
            Vsm[(dq * 4 + 3) * KVPAD + j] = vv.w;
        }
        __syncthreads();

        // ---- S = Q * K^T ----
        float s[8][4] = {};
        #pragma unroll
        for (int kb = 0; kb < 8; kb++) {
            #pragma unroll
            for (int fn = 0; fn < 8; fn++) {
                uint32_t bb[2];
                bb[0] = Ksm[(fn * 8 + r4) * KVPAD + kb * 8 + c4];
                bb[1] = Ksm[(fn * 8 + r4) * KVPAD + kb * 8 + c4 + 4];
                mma8(s[fn], qf[kb], bb);
            }
        }

        // ---- online softmax (quad = one row) ----
        float mt0 = -3.0e38f, mt1 = -3.0e38f;
        #pragma unroll
        for (int fn = 0; fn < 8; fn++) {
            mt0 = fmaxf(mt0, fmaxf(s[fn][0], s[fn][1]));
            mt1 = fmaxf(mt1, fmaxf(s[fn][2], s[fn][3]));
        }
        mt0 = fmaxf(mt0, __shfl_xor_sync(0xffffffffu, mt0, 1));
        mt0 = fmaxf(mt0, __shfl_xor_sync(0xffffffffu, mt0, 2));
        mt1 = fmaxf(mt1, __shfl_xor_sync(0xffffffffu, mt1, 1));
        mt1 = fmaxf(mt1, __shfl_xor_sync(0xffffffffu, mt1, 2));
        const float mn0 = fmaxf(m0, mt0), mn1 = fmaxf(m1, mt1);
        const float al0 = __expf(m0 - mn0), al1 = __expf(m1 - mn1);
        float ls0 = 0.f, ls1 = 0.f;
        #pragma unroll
        for (int fn = 0; fn < 8; fn++) {
            s[fn][0] = __expf(s[fn][0] - mn0); ls0 += s[fn][0];
            s[fn][1] = __expf(s[fn][1] - mn0); ls0 += s[fn][1];
            s[fn][2] = __expf(s[fn][2] - mn1); ls1 += s[fn][2];
            s[fn][3] = __expf(s[fn][3] - mn1); ls1 += s[fn][3];
        }
        ls0 += __shfl_xor_sync(0xffffffffu, ls0, 1);
        ls0 += __shfl_xor_sync(0xffffffffu, ls0, 2);
        ls1 += __shfl_xor_sync(0xffffffffu, ls1, 1);
        ls1 += __shfl_xor_sync(0xffffffffu, ls1, 2);
        l0 = l0 * al0 + ls0;  l1 = l1 * al1 + ls1;
        m0 = mn0;  m1 = mn1;

        #pragma unroll
        for (int fn = 0; fn < 8; fn++) {
            o[fn][0] *= al0; o[fn][1] *= al0;
            o[fn][2] *= al1; o[fn][3] *= al1;
        }

        // ---- P c-frag -> a-frag via per-warp smem ----
        {
            const int lp0 = r4 * 4 + 2 * (c4 & 1);
            const int rb  = 2 * (c4 >> 1);
            #pragma unroll
            for (int fn = 0; fn < 8; fn++) {
                Pw[(fn * 4 + rb) * 32 + lp0]         = f2t(s[fn][0]);
                Pw[(fn * 4 + rb) * 32 + lp0 + 1]     = f2t(s[fn][1]);
                Pw[(fn * 4 + rb + 1) * 32 + lp0]     = f2t(s[fn][2]);
                Pw[(fn * 4 + rb + 1) * 32 + lp0 + 1] = f2t(s[fn][3]);
            }
        }
        __syncwarp();

        // ---- O += P * V ----
        #pragma unroll
        for (int kb = 0; kb < 8; kb++) {
            uint32_t a[4];
            a[0] = Pw[(kb * 4 + 0) * 32 + lane];
            a[1] = Pw[(kb * 4 + 1) * 32 + lane];
            a[2] = Pw[(kb * 4 + 2) * 32 + lane];
            a[3] = Pw[(kb * 4 + 3) * 32 + lane];
            #pragma unroll
            for (int fn = 0; fn < 8; fn++) {
                uint32_t bb[2];
                bb[0] = Vsm[(fn * 8 + r4) * KVPAD + kb * 8 + c4];
                bb[1] = Vsm[(fn * 8 + r4) * KVPAD + kb * 8 + c4 + 4];
                mma8(o[fn], a, bb);
            }
        }
        __syncwarp();
    }

    // ---- normalize, emit tf32 bits for GEMM2 ----
    const float inv0 = 1.f / l0, inv1 = 1.f / l1;
    uint32_t* ob = out + ((size_t)b * SEQ + qr0) * INNER + h * DH;
    #pragma unroll
    for (int fn = 0; fn < 8; fn++) {
        const int col = fn * 8 + 2 * c4;
        *(uint2*)&ob[(size_t)r4 * INNER + col] =
            make_uint2(f2t(o[fn][0] * inv0), f2t(o[fn][1] * inv0));
        *(uint2*)&ob[(size_t)(r4 + 8) * INNER + col] =
            make_uint2(f2t(o[fn][2] * inv1), f2t(o[fn][3] * inv1));
    }
}

// ---------------------------------------------------------------------------
// Launch
// ---------------------------------------------------------------------------
extern "C" void kernel_launch(void* const* d_in, const int* in_sizes, int n_in,
                              void* d_out, int out_size)
{
    const float* x      = (const float*)d_in[0];
    const float* w_qkv  = (const float*)d_in[1];
    const float* w_out  = (const float*)d_in[2];
    const float* b_out  = (const float*)d_in[3];
    uint32_t* out = (uint32_t*)d_out;

    uint32_t *qkv, *att, *xt, *wqkvt, *woutt;
    cudaGetSymbolAddress((void**)&qkv,   g_qkv);
    cudaGetSymbolAddress((void**)&att,   g_att);
    cudaGetSymbolAddress((void**)&xt,    g_xt);
    cudaGetSymbolAddress((void**)&wqkvt, g_wqkvt);
    cudaGetSymbolAddress((void**)&woutt, g_woutt);

    const int M = BATCH * SEQ;   // 8192

    cudaFuncSetAttribute(gemm_tf32, cudaFuncAttributeMaxDynamicSharedMemorySize, GEMM_SMEM);
    cudaFuncSetAttribute(attn_tf32, cudaFuncAttributeMaxDynamicSharedMemorySize, ATTN_SMEM);

    // 0) pre-convert operands to tf32 bits
    conv_tf32<<<2048, 256>>>((const float4*)x,     (uint4*)xt,    (int)((size_t)M * DIM / 4));
    conv_tf32<<<1024, 256>>>((const float4*)w_qkv, (uint4*)wqkvt, (int)((size_t)DIM * 3 * INNER / 4));
    conv_tf32<<<512,  256>>>((const float4*)w_out, (uint4*)woutt, (int)((size_t)INNER * DIM / 4));

    // 1) QKV projection (emits tf32 bits)
    gemm_tf32<<<dim3(3 * INNER / 128, M / 128), 256, GEMM_SMEM>>>(
        xt, wqkvt, nullptr, qkv, M, 3 * INNER, DIM, 1);

    // 2) Flash attention (emits tf32 bits)
    attn_tf32<<<dim3(SEQ / 128, HEADS, BATCH), 256, ATTN_SMEM>>>(qkv, att);

    // 3) Output projection (fp32 + bias, final)
    gemm_tf32<<<dim3(DIM / 128, M / 128), 256, GEMM_SMEM>>>(
        att, woutt, b_out, out, M, DIM, INNER, 0);
}

// round 11
// speedup vs baseline: 1.7924x; 1.2580x over previous
#include <cuda_runtime.h>
#include <cstdint>

#define BATCH 8
#define SEQ   1024
#define DIM   1024
#define HEADS 16
#define DH    64
#define INNER 1024
#define QKV_STRIDE (3 * INNER)

// Scratch (static device arrays: the sanctioned no-alloc workaround)
__device__ uint32_t g_qkv[(size_t)BATCH * SEQ * 3 * INNER];   // tf32 bits
__device__ uint32_t g_att[(size_t)BATCH * SEQ * INNER];       // tf32 bits
__device__ uint32_t g_xt[(size_t)BATCH * SEQ * DIM];          // x as tf32 bits
__device__ uint32_t g_wqkvt[(size_t)DIM * 3 * INNER];         // w_qkv as tf32 bits
__device__ uint32_t g_woutt[(size_t)INNER * DIM];             // w_out as tf32 bits

// ---------------------------------------------------------------------------
// helpers
// ---------------------------------------------------------------------------
__device__ __forceinline__ uint32_t f2t(float x) {
    uint32_t r;
    asm("cvt.rna.tf32.f32 %0, %1;" : "=r"(r) : "f"(x));
    return r;
}
__device__ __forceinline__ uint4 f2t4(float4 v) {
    return make_uint4(f2t(v.x), f2t(v.y), f2t(v.z), f2t(v.w));
}
__device__ __forceinline__ float ex2(float x) {
    float r;
    asm("ex2.approx.ftz.f32 %0, %1;" : "=f"(r) : "f"(x));
    return r;
}
__device__ __forceinline__ uint32_t smem_u32(const void* p) {
    uint32_t a;
    asm("{ .reg .u64 t; cvta.to.shared.u64 t, %1; cvt.u32.u64 %0, t; }" : "=r"(a) : "l"(p));
    return a;
}
__device__ __forceinline__ void cpasync16(uint32_t s, const void* g) {
    asm volatile("cp.async.cg.shared.global [%0], [%1], 16;" :: "r"(s), "l"(g));
}

// m16n8k8 tf32 MMA, fp32 accumulate. A row-major, B col-major.
__device__ __forceinline__ void mma8(float* c, const uint32_t* a, const uint32_t* b) {
    asm volatile(
        "mma.sync.aligned.m16n8k8.row.col.f32.tf32.tf32.f32 "
        "{%0,%1,%2,%3}, {%4,%5,%6,%7}, {%8,%9}, {%0,%1,%2,%3};\n"
        : "+f"(c[0]), "+f"(c[1]), "+f"(c[2]), "+f"(c[3])
        : "r"(a[0]), "r"(a[1]), "r"(a[2]), "r"(a[3]), "r"(b[0]), "r"(b[1]));
}

// ---------------------------------------------------------------------------
// fp32 -> tf32-bits converter
// ---------------------------------------------------------------------------
__global__ void conv_tf32(const float4* __restrict__ in, uint4* __restrict__ out, int n4) {
    for (int i = blockIdx.x * blockDim.x + threadIdx.x; i < n4; i += gridDim.x * blockDim.x)
        out[i] = f2t4(in[i]);
}

// ---------------------------------------------------------------------------
// tf32 GEMM on pre-converted bits: C = A*B (+bias).
// BM=BN=128, BK=16, 256 threads, 8 warps (2m x 4n), warp tile 64x32.
// 4-stage cp.async pipeline; As [m][k] LDA=20, Bs [k][n] LDB=136.
// ---------------------------------------------------------------------------
#define LDA 20
#define LDB 136
#define STG_WORDS (128 * LDA + 16 * LDB)          // 4736 words / stage
#define GEMM_SMEM (4 * STG_WORDS * 4)             // 75776 bytes

__global__ __launch_bounds__(256, 2) void gemm_tf32(
    const uint32_t* __restrict__ A, const uint32_t* __restrict__ B,
    const float* __restrict__ bias, uint32_t* __restrict__ C,
    int M, int N, int K, int out_tf32)
{
    extern __shared__ uint32_t sm[];
    const uint32_t sbase = smem_u32(sm);

    const int tid  = threadIdx.x;
    const int lane = tid & 31;
    const int warp = tid >> 5;
    const int row0 = blockIdx.y * 128;
    const int col0 = blockIdx.x * 128;

    const int wm = (warp >> 2) * 64;
    const int wn = (warp & 3) * 32;
    const int r4 = lane >> 2, c4 = lane & 3;

    float acc[4][4][4] = {};

    const int nch = K / 16;

    auto issue = [&](int c, int st) {
        const int kt = c * 16;
        const uint32_t abase = sbase + st * STG_WORDS * 4;
        const uint32_t bbase = abase + 128 * LDA * 4;
        #pragma unroll
        for (int it = 0; it < 2; it++) {
            int idx = tid + it * 256;                 // 0..511
            int m = idx >> 2, k0 = (idx & 3) * 4;
            cpasync16(abase + (m * LDA + k0) * 4,
                      A + (size_t)(row0 + m) * K + kt + k0);
            int kr = idx >> 5, nq = (idx & 31) * 4;
            cpasync16(bbase + (kr * LDB + nq) * 4,
                      B + (size_t)(kt + kr) * N + col0 + nq);
        }
        asm volatile("cp.async.commit_group;" ::: "memory");
    };

    issue(0, 0);
    issue(1, 1);
    issue(2, 2);

    for (int c = 0; c < nch; c++) {
        const int rem = nch - 1 - c;
        if (rem >= 2)      asm volatile("cp.async.wait_group 2;" ::: "memory");
        else if (rem == 1) asm volatile("cp.async.wait_group 1;" ::: "memory");
        else               asm volatile("cp.async.wait_group 0;" ::: "memory");
        __syncthreads();

        const uint32_t* As = sm + (c & 3) * STG_WORDS;
        const uint32_t* Bs = As + 128 * LDA;

        #pragma unroll
        for (int kk = 0; kk < 2; kk++) {
            const int kc = kk * 8 + c4;
            uint32_t a[4][4], b[4][2];
            #pragma unroll
            for (int fm = 0; fm < 4; fm++) {
                const int r = wm + fm * 16 + r4;
                a[fm][0] = As[r * LDA + kc];
                a[fm][1] = As[(r + 8) * LDA + kc];
                a[fm][2] = As[r * LDA + kc + 4];
                a[fm][3] = As[(r + 8) * LDA + kc + 4];
            }
            #pragma unroll
            for (int fn = 0; fn < 4; fn++) {
                const int n = wn + fn * 8 + r4;
                b[fn][0] = Bs[kc * LDB + n];
                b[fn][1] = Bs[(kc + 4) * LDB + n];
            }
            #pragma unroll
            for (int fm = 0; fm < 4; fm++)
                #pragma unroll
                for (int fn = 0; fn < 4; fn++)
                    mma8(acc[fm][fn], a[fm], b[fn]);
        }

        if (c + 3 < nch) issue(c + 3, (c + 3) & 3);
    }

    // Epilogue
    #pragma unroll
    for (int fm = 0; fm < 4; fm++) {
        #pragma unroll
        for (int fn = 0; fn < 4; fn++) {
            const int row = row0 + wm + fm * 16 + r4;
            const int col = col0 + wn + fn * 8 + c4 * 2;
            uint32_t* c0 = C + (size_t)row * N + col;
            uint32_t* c1 = C + (size_t)(row + 8) * N + col;
            if (out_tf32) {
                *(uint2*)c0 = make_uint2(f2t(acc[fm][fn][0]), f2t(acc[fm][fn][1]));
                *(uint2*)c1 = make_uint2(f2t(acc[fm][fn][2]), f2t(acc[fm][fn][3]));
            } else {
                float b0 = 0.f, b1 = 0.f;
                if (bias) { b0 = bias[col]; b1 = bias[col + 1]; }
                *(float2*)c0 = make_float2(acc[fm][fn][0] + b0, acc[fm][fn][1] + b1);
                *(float2*)c1 = make_float2(acc[fm][fn][2] + b0, acc[fm][fn][3] + b1);
            }
        }
    }
}

// ---------------------------------------------------------------------------
// Flash attention. CTA = 128 query rows of one (b,h); 128 threads, 4 warps.
// Warp owns 32 rows (2 m-tiles of 16) x 64 cols: each K/V b-frag feeds 2 MMAs.
// Q frags resident in registers. Softmax in exp2 domain (log2e folded into
// Q prescale). V^T stored with XOR swizzle: conflict-free b-frag loads,
// 2-way stores. P round-trips per-warp smem (__syncwarp only).
// ---------------------------------------------------------------------------
#define KVPAD 68
#define ATTN_SMEM ((2 * 64 * KVPAD + 4 * 2048) * 4)   // 67584 bytes

__global__ __launch_bounds__(128) void attn_tf32(
    const uint32_t* __restrict__ qkv, uint32_t* __restrict__ out)
{
    extern __shared__ uint32_t sm[];
    uint32_t* Ksm = sm;                     // [j(64)][KVPAD]
    uint32_t* Vsm = sm + 64 * KVPAD;        // [d(64)][ j ^ 4*((d>>3)&7) ]
    uint32_t* Psm = sm + 2 * 64 * KVPAD;    // per-warp 2048 words

    const int tid  = threadIdx.x;
    const int lane = tid & 31;
    const int warp = tid >> 5;
    const int r4 = lane >> 2, c4 = lane & 3;
    const int qt = blockIdx.x, h = blockIdx.y, b = blockIdx.z;
    const int qr0 = qt * 128 + warp * 32;

    const uint32_t* qbase = qkv + ((size_t)b * SEQ + qr0) * QKV_STRIDE + h * DH;
    const uint32_t* kbase = qkv + (size_t)b * SEQ * QKV_STRIDE + INNER     + h * DH;
    const uint32_t* vbase = qkv + (size_t)b * SEQ * QKV_STRIDE + 2 * INNER + h * DH;

    // Q fragments: 32 rows as 2 m-tiles, prescaled by log2(e)/sqrt(Dh)
    const float QS = 0.125f * 1.44269504088896340736f;
    uint32_t qf[8][2][4];
    #pragma unroll
    for (int kb = 0; kb < 8; kb++) {
        const int col = kb * 8 + c4;
        #pragma unroll
        for (int m2 = 0; m2 < 2; m2++) {
            const int rb = m2 * 16;
            qf[kb][m2][0] = f2t(__uint_as_float(qbase[(size_t)(rb + r4) * QKV_STRIDE + col]) * QS);
            qf[kb][m2][1] = f2t(__uint_as_float(qbase[(size_t)(rb + r4 + 8) * QKV_STRIDE + col]) * QS);
            qf[kb][m2][2] = f2t(__uint_as_float(qbase[(size_t)(rb + r4) * QKV_STRIDE + col + 4]) * QS);
            qf[kb][m2][3] = f2t(__uint_as_float(qbase[(size_t)(rb + r4 + 8) * QKV_STRIDE + col + 4]) * QS);
        }
    }

    float mrun[2][2] = {{-3.0e38f, -3.0e38f}, {-3.0e38f, -3.0e38f}};
    float lrun[2][2] = {{0.f, 0.f}, {0.f, 0.f}};
    float o[2][8][4] = {};
    uint32_t* Pw = Psm + warp * 2048;

    for (int t = 0; t < 16; t++) {
        __syncthreads();   // previous tile fully consumed
        const uint32_t* kt_ = kbase + (size_t)t * 64 * QKV_STRIDE;
        const uint32_t* vt_ = vbase + (size_t)t * 64 * QKV_STRIDE;
        #pragma unroll
        for (int it = 0; it < 8; it++) {
            int idx = it * 128 + tid;            // 0..1023 uint4s
            int j = idx >> 4, dq = idx & 15;
            uint4 kv = *(const uint4*)(kt_ + (size_t)j * QKV_STRIDE + dq * 4);
            *(uint4*)&Ksm[j * KVPAD + dq * 4] = kv;
            uint4 vv = *(const uint4*)(vt_ + (size_t)j * QKV_STRIDE + dq * 4);
            const int swc = j ^ (4 * ((dq >> 1) & 7));
            Vsm[(dq * 4 + 0) * KVPAD + swc] = vv.x;
            Vsm[(dq * 4 + 1) * KVPAD + swc] = vv.y;
            Vsm[(dq * 4 + 2) * KVPAD + swc] = vv.z;
            Vsm[(dq * 4 + 3) * KVPAD + swc] = vv.w;
        }
        __syncthreads();

        // ---- S = Q * K^T : 32 rows x 64 cols (b-frags shared across m2) ----
        float s[2][8][4] = {};
        #pragma unroll
        for (int kb = 0; kb < 8; kb++) {
            #pragma unroll
            for (int fn = 0; fn < 8; fn++) {
                uint32_t bb[2];
                bb[0] = Ksm[(fn * 8 + r4) * KVPAD + kb * 8 + c4];
                bb[1] = Ksm[(fn * 8 + r4) * KVPAD + kb * 8 + c4 + 4];
                mma8(s[0][fn], qf[kb][0], bb);
                mma8(s[1][fn], qf[kb][1], bb);
            }
        }

        // ---- online softmax (exp2 domain), P -> per-warp smem a-frags ----
        #pragma unroll
        for (int m2 = 0; m2 < 2; m2++) {
            float mt0 = -3.0e38f, mt1 = -3.0e38f;
            #pragma unroll
            for (int fn = 0; fn < 8; fn++) {
                mt0 = fmaxf(mt0, fmaxf(s[m2][fn][0], s[m2][fn][1]));
                mt1 = fmaxf(mt1, fmaxf(s[m2][fn][2], s[m2][fn][3]));
            }
            mt0 = fmaxf(mt0, __shfl_xor_sync(0xffffffffu, mt0, 1));
            mt0 = fmaxf(mt0, __shfl_xor_sync(0xffffffffu, mt0, 2));
            mt1 = fmaxf(mt1, __shfl_xor_sync(0xffffffffu, mt1, 1));
            mt1 = fmaxf(mt1, __shfl_xor_sync(0xffffffffu, mt1, 2));
            const float mn0 = fmaxf(mrun[m2][0], mt0);
            const float mn1 = fmaxf(mrun[m2][1], mt1);
            const float al0 = ex2(mrun[m2][0] - mn0);
            const float al1 = ex2(mrun[m2][1] - mn1);
            float ls0 = 0.f, ls1 = 0.f;
            #pragma unroll
            for (int fn = 0; fn < 8; fn++) {
                s[m2][fn][0] = ex2(s[m2][fn][0] - mn0); ls0 += s[m2][fn][0];
                s[m2][fn][1] = ex2(s[m2][fn][1] - mn0); ls0 += s[m2][fn][1];
                s[m2][fn][2] = ex2(s[m2][fn][2] - mn1); ls1 += s[m2][fn][2];
                s[m2][fn][3] = ex2(s[m2][fn][3] - mn1); ls1 += s[m2][fn][3];
            }
            ls0 += __shfl_xor_sync(0xffffffffu, ls0, 1);
            ls0 += __shfl_xor_sync(0xffffffffu, ls0, 2);
            ls1 += __shfl_xor_sync(0xffffffffu, ls1, 1);
            ls1 += __shfl_xor_sync(0xffffffffu, ls1, 2);
            lrun[m2][0] = lrun[m2][0] * al0 + ls0;
            lrun[m2][1] = lrun[m2][1] * al1 + ls1;
            mrun[m2][0] = mn0;  mrun[m2][1] = mn1;

            #pragma unroll
            for (int fn = 0; fn < 8; fn++) {
                o[m2][fn][0] *= al0; o[m2][fn][1] *= al0;
                o[m2][fn][2] *= al1; o[m2][fn][3] *= al1;
            }

            // c-frag -> a-frag repack
            const int lp0 = r4 * 4 + 2 * (c4 & 1);
            const int rb  = 2 * (c4 >> 1);
            uint32_t* Pm = Pw + m2 * 1024;
            #pragma unroll
            for (int fn = 0; fn < 8; fn++) {
                Pm[(fn * 4 + rb) * 32 + lp0]         = f2t(s[m2][fn][0]);
                Pm[(fn * 4 + rb) * 32 + lp0 + 1]     = f2t(s[m2][fn][1]);
                Pm[(fn * 4 + rb + 1) * 32 + lp0]     = f2t(s[m2][fn][2]);
                Pm[(fn * 4 + rb + 1) * 32 + lp0 + 1] = f2t(s[m2][fn][3]);
            }
        }
        __syncwarp();

        // ---- O += P * V (V b-frags shared across m2; swizzled loads) ----
        #pragma unroll
        for (int kb = 0; kb < 8; kb++) {
            uint32_t a0[4], a1[4];
            #pragma unroll
            for (int r = 0; r < 4; r++) {
                a0[r] = Pw[(kb * 4 + r) * 32 + lane];
                a1[r] = Pw[1024 + (kb * 4 + r) * 32 + lane];
            }
            #pragma unroll
            for (int fn = 0; fn < 8; fn++) {
                const int d = fn * 8 + r4;
                const int sw = 4 * fn;
                uint32_t bb[2];
                bb[0] = Vsm[d * KVPAD + ((kb * 8 + c4) ^ sw)];
                bb[1] = Vsm[d * KVPAD + ((kb * 8 + c4 + 4) ^ sw)];
                mma8(o[0][fn], a0, bb);
                mma8(o[1][fn], a1, bb);
            }
        }
        __syncwarp();   // P reads done before next tile's P writes
    }

    // ---- normalize, emit tf32 bits for GEMM2 ----
    #pragma unroll
    for (int m2 = 0; m2 < 2; m2++) {
        const float inv0 = 1.f / lrun[m2][0];
        const float inv1 = 1.f / lrun[m2][1];
        uint32_t* ob = out + ((size_t)b * SEQ + qr0 + m2 * 16) * INNER + h * DH;
        #pragma unroll
        for (int fn = 0; fn < 8; fn++) {
            const int col = fn * 8 + 2 * c4;
            *(uint2*)&ob[(size_t)r4 * INNER + col] =
                make_uint2(f2t(o[m2][fn][0] * inv0), f2t(o[m2][fn][1] * inv0));
            *(uint2*)&ob[(size_t)(r4 + 8) * INNER + col] =
                make_uint2(f2t(o[m2][fn][2] * inv1), f2t(o[m2][fn][3] * inv1));
        }
    }
}

// ---------------------------------------------------------------------------
// Launch
// ---------------------------------------------------------------------------
extern "C" void kernel_launch(void* const* d_in, const int* in_sizes, int n_in,
                              void* d_out, int out_size)
{
    const float* x      = (const float*)d_in[0];
    const float* w_qkv  = (const float*)d_in[1];
    const float* w_out  = (const float*)d_in[2];
    const float* b_out  = (const float*)d_in[3];
    uint32_t* out = (uint32_t*)d_out;

    uint32_t *qkv, *att, *xt, *wqkvt, *woutt;
    cudaGetSymbolAddress((void**)&qkv,   g_qkv);
    cudaGetSymbolAddress((void**)&att,   g_att);
    cudaGetSymbolAddress((void**)&xt,    g_xt);
    cudaGetSymbolAddress((void**)&wqkvt, g_wqkvt);
    cudaGetSymbolAddress((void**)&woutt, g_woutt);

    const int M = BATCH * SEQ;   // 8192

    cudaFuncSetAttribute(gemm_tf32, cudaFuncAttributeMaxDynamicSharedMemorySize, GEMM_SMEM);
    cudaFuncSetAttribute(attn_tf32, cudaFuncAttributeMaxDynamicSharedMemorySize, ATTN_SMEM);

    // 0) pre-convert operands to tf32 bits
    conv_tf32<<<2048, 256>>>((const float4*)x,     (uint4*)xt,    (int)((size_t)M * DIM / 4));
    conv_tf32<<<1024, 256>>>((const float4*)w_qkv, (uint4*)wqkvt, (int)((size_t)DIM * 3 * INNER / 4));
    conv_tf32<<<512,  256>>>((const float4*)w_out, (uint4*)woutt, (int)((size_t)INNER * DIM / 4));

    // 1) QKV projection (emits tf32 bits)
    gemm_tf32<<<dim3(3 * INNER / 128, M / 128), 256, GEMM_SMEM>>>(
        xt, wqkvt, nullptr, qkv, M, 3 * INNER, DIM, 1);

    // 2) Flash attention (emits tf32 bits)
    attn_tf32<<<dim3(SEQ / 128, HEADS, BATCH), 128, ATTN_SMEM>>>(qkv, att);

    // 3) Output projection (fp32 + bias, final)
    gemm_tf32<<<dim3(DIM / 128, M / 128), 256, GEMM_SMEM>>>(
        att, woutt, b_out, out, M, DIM, INNER, 0);
}